// round 1
// baseline (speedup 1.0000x reference)
#include <cuda_runtime.h>

#define BATCH   8
#define TSTEPS  12
#define CIN_X   5
#define HID     16
#define CIN_ALL (CIN_X + HID)      /* 21 */
#define IMG     256
#define KW      9                  /* 3x3 */
#define WPERC   (CIN_ALL * KW)     /* 189 */
#define TILE    16
#define SH      18                 /* tile + halo rows */
#define SROW    19                 /* padded smem row stride */
#define NTHREADS 512
#define SMEM_W  (64 * WPERC)                 /* 12096 floats */
#define SMEM_IN (CIN_ALL * SH * SROW)        /* 7182 floats  */
#define SMEM_BYTES ((SMEM_W + SMEM_IN) * 4)  /* 77112 bytes  */

// Scratch state (no allocations allowed): double-buffered h, in-place c.
__device__ float g_h[2][BATCH * HID * IMG * IMG];
__device__ float g_c[BATCH * HID * IMG * IMG];

typedef unsigned long long u64;

__device__ __forceinline__ u64 pk2(float lo, float hi) {
    u64 r; asm("mov.b64 %0, {%1, %2};" : "=l"(r) : "f"(lo), "f"(hi)); return r;
}
__device__ __forceinline__ void upk2(u64 v, float &lo, float &hi) {
    asm("mov.b64 {%0, %1}, %2;" : "=f"(lo), "=f"(hi) : "l"(v));
}
// Packed dual-fp32 FMA (Blackwell FFMA2 — only reachable via PTX f32x2).
#define FFMA2(acc, a, b) asm("fma.rn.f32x2 %0, %1, %2, %0;" : "+l"(acc) : "l"(a), "l"(b))

__device__ __forceinline__ float sig_(float x)  { return 1.0f / (1.0f + __expf(-x)); }
__device__ __forceinline__ float tanh_(float x) { return 2.0f / (1.0f + __expf(-2.0f * x)) - 1.0f; }

// One ConvLSTM timestep, fully fused: 3x3 conv (x_t ++ h_prev) -> gates -> c,h update.
// Block: 16x16 spatial tile, all 16 hidden channels. Warp w == hidden channel w
// (weight smem reads are warp-uniform -> conflict-free broadcast).
// Thread: 8 consecutive pixels (one row) x 4 gate channels, f32x2 accumulators.
__global__ void __launch_bounds__(NTHREADS, 1)
lstm_step_kernel(const float* __restrict__ xall, const float* __restrict__ Wc,
                 const float* __restrict__ bc, int t)
{
    extern __shared__ float smem[];
    float* s_w  = smem;            // [64][189]
    float* s_in = smem + SMEM_W;   // [21][18][19]

    const int tid = threadIdx.x;
    const int b  = blockIdx.z;
    const int y0 = blockIdx.y * TILE;
    const int x0 = blockIdx.x * TILE;
    const int first = (t == 0);
    const int ncin  = first ? CIN_X : CIN_ALL;   // t=0: h_prev == 0, skip h channels

    const float* h_prev = g_h[t & 1];
    float*       h_next = g_h[(t + 1) & 1];

    // Weights -> smem (vectorized; 12096 floats = 3024 float4)
    {
        const float4* src = (const float4*)Wc;
        float4* dst = (float4*)s_w;
        #pragma unroll 1
        for (int i = tid; i < SMEM_W / 4; i += NTHREADS) dst[i] = src[i];
    }
    // Input tile (+1 halo all sides) -> smem. Channels 0..4 from x_t, 5..20 from h_prev.
    {
        const int ntile = ncin * SH * SH;
        #pragma unroll 1
        for (int i = tid; i < ntile; i += NTHREADS) {
            int ch  = i / (SH * SH);
            int rem = i - ch * SH * SH;
            int r   = rem / SH;
            int cc  = rem - r * SH;
            int gy = y0 + r - 1, gx = x0 + cc - 1;
            float v = 0.0f;
            if ((unsigned)gy < IMG && (unsigned)gx < IMG) {
                if (ch < CIN_X)
                    v = xall[(((b * TSTEPS + t) * CIN_X + ch) << 16) + (gy << 8) + gx];
                else
                    v = h_prev[((b * HID + (ch - CIN_X)) << 16) + (gy << 8) + gx];
            }
            s_in[ch * (SH * SROW) + r * SROW + cc] = v;
        }
    }
    __syncthreads();

    const int hid = tid >> 5;        // warp-uniform
    const int grp = tid & 31;
    const int row = grp >> 1;        // 0..15
    const int xg  = grp & 1;         // 0..1  (pixels xg*8 .. xg*8+7)

    u64 acc[4][4];                   // [gate][pixel-pair]
    #pragma unroll
    for (int g = 0; g < 4; ++g)
        #pragma unroll
        for (int j = 0; j < 4; ++j) acc[g][j] = 0ULL;

    const float* wh = s_w + hid * WPERC;
    #pragma unroll 1
    for (int ci = 0; ci < ncin; ++ci) {
        const float* wci = wh + ci * KW;
        const float* inc = s_in + ci * (SH * SROW) + xg * 8;
        #pragma unroll
        for (int ky = 0; ky < 3; ++ky) {
            const float* inr = inc + (row + ky) * SROW;
            float r0 = inr[0], r1 = inr[1], r2 = inr[2], r3 = inr[3], r4 = inr[4];
            float r5 = inr[5], r6 = inr[6], r7 = inr[7], r8 = inr[8], r9 = inr[9];
            // sliding-window pixel pairs: pN = (rN, rN+1)
            u64 p0 = pk2(r0, r1), p1 = pk2(r1, r2), p2 = pk2(r2, r3);
            u64 p3 = pk2(r3, r4), p4 = pk2(r4, r5), p5 = pk2(r5, r6);
            u64 p6 = pk2(r6, r7), p7 = pk2(r7, r8), p8 = pk2(r8, r9);
            #pragma unroll
            for (int g = 0; g < 4; ++g) {
                const float* wg = wci + g * (HID * WPERC) + ky * 3;
                float w0s = wg[0], w1s = wg[1], w2s = wg[2];
                u64 w0 = pk2(w0s, w0s), w1 = pk2(w1s, w1s), w2 = pk2(w2s, w2s);
                FFMA2(acc[g][0], p0, w0); FFMA2(acc[g][1], p2, w0);
                FFMA2(acc[g][2], p4, w0); FFMA2(acc[g][3], p6, w0);
                FFMA2(acc[g][0], p1, w1); FFMA2(acc[g][1], p3, w1);
                FFMA2(acc[g][2], p5, w1); FFMA2(acc[g][3], p7, w1);
                FFMA2(acc[g][0], p2, w2); FFMA2(acc[g][1], p4, w2);
                FFMA2(acc[g][2], p6, w2); FFMA2(acc[g][3], p8, w2);
            }
        }
    }

    // Epilogue: gates + state update for 8 pixels.
    const float bi  = bc[hid];
    const float bfv = bc[hid + 16];
    const float bo  = bc[hid + 32];
    const float bg  = bc[hid + 48];
    const int base = ((b * HID + hid) << 16) + ((y0 + row) << 8) + x0 + xg * 8;

    float cold[8];
    if (!first) {
        float4 ca = *(const float4*)(g_c + base);
        float4 cb = *(const float4*)(g_c + base + 4);
        cold[0] = ca.x; cold[1] = ca.y; cold[2] = ca.z; cold[3] = ca.w;
        cold[4] = cb.x; cold[5] = cb.y; cold[6] = cb.z; cold[7] = cb.w;
    } else {
        #pragma unroll
        for (int p = 0; p < 8; ++p) cold[p] = 0.0f;
    }

    float cn[8], hn[8];
    #pragma unroll
    for (int j = 0; j < 4; ++j) {
        float iv0, iv1, fv0, fv1, ov0, ov1, gv0, gv1;
        upk2(acc[0][j], iv0, iv1);
        upk2(acc[1][j], fv0, fv1);
        upk2(acc[2][j], ov0, ov1);
        upk2(acc[3][j], gv0, gv1);
        {
            int p = 2 * j;
            float i = sig_(iv0 + bi),  f = sig_(fv0 + bfv);
            float o = sig_(ov0 + bo),  g = tanh_(gv0 + bg);
            float c = f * cold[p] + i * g;
            cn[p] = c; hn[p] = o * tanh_(c);
        }
        {
            int p = 2 * j + 1;
            float i = sig_(iv1 + bi),  f = sig_(fv1 + bfv);
            float o = sig_(ov1 + bo),  g = tanh_(gv1 + bg);
            float c = f * cold[p] + i * g;
            cn[p] = c; hn[p] = o * tanh_(c);
        }
    }
    *(float4*)(g_c + base)        = make_float4(cn[0], cn[1], cn[2], cn[3]);
    *(float4*)(g_c + base + 4)    = make_float4(cn[4], cn[5], cn[6], cn[7]);
    *(float4*)(h_next + base)     = make_float4(hn[0], hn[1], hn[2], hn[3]);
    *(float4*)(h_next + base + 4) = make_float4(hn[4], hn[5], hn[6], hn[7]);
}

// Final 1x1 conv: out[b,0,:,:] = sum_j Wf[j] * h_last[b,j,:,:] + bf
__global__ void final_conv_kernel(const float* __restrict__ Wf,
                                  const float* __restrict__ bfin,
                                  float* __restrict__ out)
{
    const int total4 = BATCH * IMG * IMG / 4;
    int idx4 = blockIdx.x * blockDim.x + threadIdx.x;
    if (idx4 >= total4) return;
    const float* h = g_h[TSTEPS & 1];   // g_h[0] holds h_last after 12 steps
    int b    = idx4 >> 14;              // 16384 float4 per batch image
    int pix4 = idx4 & 16383;
    float w[HID];
    #pragma unroll
    for (int j = 0; j < HID; ++j) w[j] = Wf[j];
    float4 a;
    float bv = bfin[0];
    a.x = bv; a.y = bv; a.z = bv; a.w = bv;
    #pragma unroll
    for (int j = 0; j < HID; ++j) {
        float4 v = *(const float4*)(h + ((b * HID + j) << 16) + pix4 * 4);
        a.x += w[j] * v.x; a.y += w[j] * v.y;
        a.z += w[j] * v.z; a.w += w[j] * v.w;
    }
    ((float4*)out)[idx4] = a;
}

extern "C" void kernel_launch(void* const* d_in, const int* in_sizes, int n_in,
                              void* d_out, int out_size)
{
    const float* x  = (const float*)d_in[0];
    const float* Wc = (const float*)d_in[1];
    const float* bc = (const float*)d_in[2];
    const float* Wf = (const float*)d_in[3];
    const float* bf = (const float*)d_in[4];
    float* out = (float*)d_out;

    cudaFuncSetAttribute(lstm_step_kernel,
                         cudaFuncAttributeMaxDynamicSharedMemorySize, SMEM_BYTES);

    dim3 grid(IMG / TILE, IMG / TILE, BATCH);
    for (int t = 0; t < TSTEPS; ++t)
        lstm_step_kernel<<<grid, NTHREADS, SMEM_BYTES>>>(x, Wc, bc, t);

    const int total4 = BATCH * IMG * IMG / 4;
    final_conv_kernel<<<(total4 + 255) / 256, 256>>>(Wf, bf, out);
}

// round 2
// speedup vs baseline: 1.0103x; 1.0103x over previous
#include <cuda_runtime.h>

#define BATCH   8
#define TSTEPS  12
#define CIN_X   5
#define HID     16
#define CIN_ALL (CIN_X + HID)      /* 21 */
#define IMG     256
#define KW      9                  /* 3x3 */
#define WPERC   (CIN_ALL * KW)     /* 189 */
#define TILE    16
#define NTHREADS 512

/* smem layout (floats):
   [0, 24192)                weights as duplicated float2 (64*189 pairs)
   [24192, 24192+6804)       copy A: [21 ci][18 rows][18 floats] (cols 0..15 + pad)
   [.., +8316)               copy B: [21 ci][18 rows][22 floats] (cols -1..16 at idx m+1, + pad)
*/
#define SMEM_W2   (64 * WPERC)             /* 12096 float2 = 24192 floats */
#define SA        18
#define A_PER_CI  (18 * SA)                /* 324 */
#define SB        22
#define B_PER_CI  (18 * SB)                /* 396 */
#define A_OFF     (SMEM_W2 * 2)            /* 24192 */
#define B_OFF     (A_OFF + CIN_ALL * A_PER_CI)   /* 30996 */
#define SMEM_FLOATS (B_OFF + CIN_ALL * B_PER_CI) /* 39312 */
#define SMEM_BYTES  (SMEM_FLOATS * 4)            /* 157248 */

__device__ float g_h[2][BATCH * HID * IMG * IMG];
__device__ float g_c[BATCH * HID * IMG * IMG];

typedef unsigned long long u64;

__device__ __forceinline__ void upk2(u64 v, float &lo, float &hi) {
    asm("mov.b64 {%0, %1}, %2;" : "=f"(lo), "=f"(hi) : "l"(v));
}
#define FFMA2(acc, a, b) asm("fma.rn.f32x2 %0, %1, %2, %0;" : "+l"(acc) : "l"(a), "l"(b))

__device__ __forceinline__ float sig_(float x)  { return 1.0f / (1.0f + __expf(-x)); }
__device__ __forceinline__ float tanh_(float x) { return 2.0f / (1.0f + __expf(-2.0f * x)) - 1.0f; }

// One fused ConvLSTM step. Block = 16x16 tile x 16 hidden channels (warp==hid).
// Lane: row = lane&15, xg = lane>>4 (half-warp spans 16 rows -> conflict-free LDS.64).
// Thread: 8 pixels (4 f32x2 pairs) x 4 gates.
__global__ void __launch_bounds__(NTHREADS, 1)
lstm_step_kernel(const float* __restrict__ xall, const float* __restrict__ Wc,
                 const float* __restrict__ bc, int t)
{
    extern __shared__ float smem[];
    float2* s_w2 = (float2*)smem;
    float*  s_A  = smem + A_OFF;
    float*  s_B  = smem + B_OFF;

    const int tid = threadIdx.x;
    const int b  = blockIdx.z;
    const int y0 = blockIdx.y * TILE;
    const int x0 = blockIdx.x * TILE;
    const int first = (t == 0);
    const int ncin  = first ? CIN_X : CIN_ALL;

    const float* h_prev = g_h[t & 1];
    float*       h_next = g_h[(t + 1) & 1];

    // Weights -> smem, duplicated (w,w) so FFMA2 weight operand is one LDS.64 broadcast.
    #pragma unroll 1
    for (int i = tid; i < SMEM_W2; i += NTHREADS) {
        float w = Wc[i];
        s_w2[i] = make_float2(w, w);
    }
    // Input tile (+halo) -> two phase-shifted smem copies.
    {
        const int ntile = ncin * 18 * SA;   // iterate (ci, r, mi) mi=m+1 in 0..17
        #pragma unroll 1
        for (int i = tid; i < ntile; i += NTHREADS) {
            int ci  = i / (18 * SA);
            int rem = i - ci * (18 * SA);
            int r   = rem / SA;
            int mi  = rem - r * SA;
            int m   = mi - 1;                  // logical col offset -1..16
            int gy = y0 + r - 1, gx = x0 + m;
            float v = 0.0f;
            if ((unsigned)gy < IMG && (unsigned)gx < IMG) {
                if (ci < CIN_X)
                    v = xall[(((b * TSTEPS + t) * CIN_X + ci) << 16) + (gy << 8) + gx];
                else
                    v = h_prev[((b * HID + (ci - CIN_X)) << 16) + (gy << 8) + gx];
            }
            s_B[ci * B_PER_CI + r * SB + mi] = v;
            if ((unsigned)m < 16u)
                s_A[ci * A_PER_CI + r * SA + m] = v;
        }
    }
    __syncthreads();

    const int hid = tid >> 5;        // warp-uniform
    const int lane = tid & 31;
    const int row = lane & 15;
    const int xg  = lane >> 4;

    u64 acc[4][4];
    #pragma unroll
    for (int g = 0; g < 4; ++g)
        #pragma unroll
        for (int j = 0; j < 4; ++j) acc[g][j] = 0ULL;

    const u64* sw64 = (const u64*)smem;   // weight pairs, u64 view

    #pragma unroll 1
    for (int ci = 0; ci < ncin; ++ci) {
        #pragma unroll
        for (int ky = 0; ky < 3; ++ky) {
            const int r = row + ky;
            const u64* ar = (const u64*)(s_A + ci * A_PER_CI + r * SA) + xg * 4;
            const u64* br = (const u64*)(s_B + ci * B_PER_CI + r * SB) + xg * 4;
            // left taps (x-1,x), center (x,x+1), right (x+1,x+2) — all aligned LDS.64
            u64 l0 = br[0], l1 = br[1], l2 = br[2], l3 = br[3];
            u64 c0 = ar[0], c1 = ar[1], c2 = ar[2], c3 = ar[3];
            u64 r0 = br[1], r1 = br[2], r2 = br[3], r3 = br[4];
            const int wb0 = hid * WPERC + ci * 9 + ky * 3;
            #pragma unroll
            for (int g = 0; g < 4; ++g) {
                const u64* wg = sw64 + wb0 + g * (HID * WPERC);
                u64 w0 = wg[0], w1 = wg[1], w2 = wg[2];
                FFMA2(acc[g][0], l0, w0); FFMA2(acc[g][1], l1, w0);
                FFMA2(acc[g][2], l2, w0); FFMA2(acc[g][3], l3, w0);
                FFMA2(acc[g][0], c0, w1); FFMA2(acc[g][1], c1, w1);
                FFMA2(acc[g][2], c2, w1); FFMA2(acc[g][3], c3, w1);
                FFMA2(acc[g][0], r0, w2); FFMA2(acc[g][1], r1, w2);
                FFMA2(acc[g][2], r2, w2); FFMA2(acc[g][3], r3, w2);
            }
        }
    }

    // Epilogue: gates + state update for 8 pixels.
    const float bi  = bc[hid];
    const float bfv = bc[hid + 16];
    const float bo  = bc[hid + 32];
    const float bg  = bc[hid + 48];
    const int base = ((b * HID + hid) << 16) + ((y0 + row) << 8) + x0 + xg * 8;

    float cold[8];
    if (!first) {
        float4 ca = *(const float4*)(g_c + base);
        float4 cb = *(const float4*)(g_c + base + 4);
        cold[0] = ca.x; cold[1] = ca.y; cold[2] = ca.z; cold[3] = ca.w;
        cold[4] = cb.x; cold[5] = cb.y; cold[6] = cb.z; cold[7] = cb.w;
    } else {
        #pragma unroll
        for (int p = 0; p < 8; ++p) cold[p] = 0.0f;
    }

    float cn[8], hn[8];
    #pragma unroll
    for (int j = 0; j < 4; ++j) {
        float iv0, iv1, fv0, fv1, ov0, ov1, gv0, gv1;
        upk2(acc[0][j], iv0, iv1);
        upk2(acc[1][j], fv0, fv1);
        upk2(acc[2][j], ov0, ov1);
        upk2(acc[3][j], gv0, gv1);
        {
            int p = 2 * j;
            float i = sig_(iv0 + bi),  f = sig_(fv0 + bfv);
            float o = sig_(ov0 + bo),  g = tanh_(gv0 + bg);
            float c = f * cold[p] + i * g;
            cn[p] = c; hn[p] = o * tanh_(c);
        }
        {
            int p = 2 * j + 1;
            float i = sig_(iv1 + bi),  f = sig_(fv1 + bfv);
            float o = sig_(ov1 + bo),  g = tanh_(gv1 + bg);
            float c = f * cold[p] + i * g;
            cn[p] = c; hn[p] = o * tanh_(c);
        }
    }
    *(float4*)(g_c + base)        = make_float4(cn[0], cn[1], cn[2], cn[3]);
    *(float4*)(g_c + base + 4)    = make_float4(cn[4], cn[5], cn[6], cn[7]);
    *(float4*)(h_next + base)     = make_float4(hn[0], hn[1], hn[2], hn[3]);
    *(float4*)(h_next + base + 4) = make_float4(hn[4], hn[5], hn[6], hn[7]);
}

// Final 1x1 conv over h_last (lives in g_h[0] after 12 steps).
__global__ void final_conv_kernel(const float* __restrict__ Wf,
                                  const float* __restrict__ bfin,
                                  float* __restrict__ out)
{
    const int total4 = BATCH * IMG * IMG / 4;
    int idx4 = blockIdx.x * blockDim.x + threadIdx.x;
    if (idx4 >= total4) return;
    const float* h = g_h[TSTEPS & 1];
    int b    = idx4 >> 14;
    int pix4 = idx4 & 16383;
    float w[HID];
    #pragma unroll
    for (int j = 0; j < HID; ++j) w[j] = Wf[j];
    float bv = bfin[0];
    float4 a; a.x = bv; a.y = bv; a.z = bv; a.w = bv;
    #pragma unroll
    for (int j = 0; j < HID; ++j) {
        float4 v = *(const float4*)(h + ((b * HID + j) << 16) + pix4 * 4);
        a.x += w[j] * v.x; a.y += w[j] * v.y;
        a.z += w[j] * v.z; a.w += w[j] * v.w;
    }
    ((float4*)out)[idx4] = a;
}

extern "C" void kernel_launch(void* const* d_in, const int* in_sizes, int n_in,
                              void* d_out, int out_size)
{
    const float* x  = (const float*)d_in[0];
    const float* Wc = (const float*)d_in[1];
    const float* bc = (const float*)d_in[2];
    const float* Wf = (const float*)d_in[3];
    const float* bf = (const float*)d_in[4];
    float* out = (float*)d_out;

    cudaFuncSetAttribute(lstm_step_kernel,
                         cudaFuncAttributeMaxDynamicSharedMemorySize, SMEM_BYTES);

    dim3 grid(IMG / TILE, IMG / TILE, BATCH);
    for (int t = 0; t < TSTEPS; ++t)
        lstm_step_kernel<<<grid, NTHREADS, SMEM_BYTES>>>(x, Wc, bc, t);

    const int total4 = BATCH * IMG * IMG / 4;
    final_conv_kernel<<<(total4 + 255) / 256, 256>>>(Wf, bf, out);
}

// round 3
// speedup vs baseline: 1.3504x; 1.3366x over previous
#include <cuda_runtime.h>

#define BATCH   8
#define TSTEPS  12
#define CIN_X   5
#define HID     16
#define CIN_ALL (CIN_X + HID)      /* 21 */
#define IMG     256
#define WPERC   (CIN_ALL * 9)      /* 189 taps per (hid) per gate */
#define TILE    16
#define NTHREADS 512

/* smem layout:
   floats [0, 12096):  weights reordered [hid16][ci21][tap9][gate4]  (48384 B)
   u64    [12096 f..): pixel tile duplicated (v,v): [21 ci][18 r][19 stride u64]
*/
#define W_FLOATS  (64 * WPERC)               /* 12096 */
#define TSTRIDE   19                         /* u64 per row (conflict-free) */
#define T_PER_CI  (18 * TSTRIDE)             /* 342 u64 */
#define TILE_U64  (CIN_ALL * T_PER_CI)       /* 7182 u64 */
#define SMEM_BYTES (W_FLOATS * 4 + TILE_U64 * 8)   /* 48384 + 57456 = 105840 */

__device__ float g_h[2][BATCH * HID * IMG * IMG];
__device__ float g_c[BATCH * HID * IMG * IMG];

typedef unsigned long long u64;

__device__ __forceinline__ u64 pk2(float lo, float hi) {
    u64 r; asm("mov.b64 %0, {%1, %2};" : "=l"(r) : "f"(lo), "f"(hi)); return r;
}
__device__ __forceinline__ void upk2(u64 v, float &lo, float &hi) {
    asm("mov.b64 {%0, %1}, %2;" : "=f"(lo), "=f"(hi) : "l"(v));
}
#define FFMA2(acc, a, b) asm("fma.rn.f32x2 %0, %1, %2, %0;" : "+l"(acc) : "l"(a), "l"(b))

__device__ __forceinline__ float sig_(float x)  { return 1.0f / (1.0f + __expf(-x)); }
__device__ __forceinline__ float tanh_(float x) { return 2.0f / (1.0f + __expf(-2.0f * x)) - 1.0f; }

// Fused ConvLSTM step. Block = 16x16 tile x 16 hid (warp==hid), 2 CTAs/SM.
// FFMA2 pairs GATES: acc_if[p] = (i,f), acc_og[p] = (o,g) for 8 pixels/thread.
// Weights: one broadcast LDS.128 per tap = 4 gates. Pixels: (v,v) dup in smem.
__global__ void __launch_bounds__(NTHREADS, 2)
lstm_step_kernel(const float* __restrict__ xall, const float* __restrict__ Wc,
                 const float* __restrict__ bc, int t)
{
    extern __shared__ float smem[];
    float* s_w  = smem;                       // [64][189] reordered -> tap-major gate4
    u64*   s_t  = (u64*)(smem + W_FLOATS);    // [21][18][19] duplicated pixels

    const int tid = threadIdx.x;
    const int b  = blockIdx.z;
    const int y0 = blockIdx.y * TILE;
    const int x0 = blockIdx.x * TILE;
    const int first = (t == 0);
    const int ncin  = first ? CIN_X : CIN_ALL;

    const float* h_prev = g_h[t & 1];
    float*       h_next = g_h[(t + 1) & 1];

    // Weights -> smem reordered: dst[hid][tap189][gate4] ; src Wc[(g*16+hid)*189 + tap]
    #pragma unroll 1
    for (int i = tid; i < 64 * WPERC / 4; i += NTHREADS) {   // 3024 items: (hid, tap)
        int hid = i / WPERC;
        int tap = i - hid * WPERC;
        float4 v;
        v.x = Wc[(hid      ) * WPERC + tap];        // gate i
        v.y = Wc[(hid + 16 ) * WPERC + tap];        // gate f
        v.z = Wc[(hid + 32 ) * WPERC + tap];        // gate o
        v.w = Wc[(hid + 48 ) * WPERC + tap];        // gate g
        ((float4*)s_w)[hid * WPERC + tap] = v;
    }
    // Input tile (+halo) duplicated (v,v) -> smem.
    {
        const int ntile = ncin * 18 * 18;
        #pragma unroll 1
        for (int i = tid; i < ntile; i += NTHREADS) {
            int ci  = i / (18 * 18);
            int rem = i - ci * (18 * 18);
            int r   = rem / 18;
            int mi  = rem - r * 18;                 // 0..17 == col offset -1..16
            int gy = y0 + r - 1, gx = x0 + mi - 1;
            float v = 0.0f;
            if ((unsigned)gy < IMG && (unsigned)gx < IMG) {
                if (ci < CIN_X)
                    v = xall[(((b * TSTEPS + t) * CIN_X + ci) << 16) + (gy << 8) + gx];
                else
                    v = h_prev[((b * HID + (ci - CIN_X)) << 16) + (gy << 8) + gx];
            }
            s_t[ci * T_PER_CI + r * TSTRIDE + mi] = pk2(v, v);
        }
    }
    __syncthreads();

    const int hid  = tid >> 5;       // warp-uniform
    const int lane = tid & 31;
    const int row  = lane & 15;
    const int xg   = lane >> 4;      // pixels xg*8 .. xg*8+7

    u64 acc_if[8], acc_og[8];
    #pragma unroll
    for (int p = 0; p < 8; ++p) { acc_if[p] = 0ULL; acc_og[p] = 0ULL; }

    #pragma unroll 1
    for (int ci = 0; ci < ncin; ++ci) {
        const u64* trow = s_t + ci * T_PER_CI + xg * 8;
        const float4* wci = (const float4*)s_w + hid * WPERC + ci * 9;
        #pragma unroll
        for (int ky = 0; ky < 3; ++ky) {
            const u64* tr = trow + (row + ky) * TSTRIDE;
            // 3 broadcast LDS.128: 4-gate weight packs for kx = 0,1,2
            float4 wv0 = wci[ky * 3 + 0];
            float4 wv1 = wci[ky * 3 + 1];
            float4 wv2 = wci[ky * 3 + 2];
            u64 wif0 = pk2(wv0.x, wv0.y), wog0 = pk2(wv0.z, wv0.w);
            u64 wif1 = pk2(wv1.x, wv1.y), wog1 = pk2(wv1.z, wv1.w);
            u64 wif2 = pk2(wv2.x, wv2.y), wog2 = pk2(wv2.z, wv2.w);
            // pixel k participates as (p = k - kx); consume each load immediately
            #pragma unroll
            for (int k = 0; k < 10; ++k) {
                u64 pix = tr[k];
                if (k <= 7)            { FFMA2(acc_if[k],     pix, wif0); FFMA2(acc_og[k],     pix, wog0); }
                if (k >= 1 && k <= 8)  { FFMA2(acc_if[k - 1], pix, wif1); FFMA2(acc_og[k - 1], pix, wog1); }
                if (k >= 2)            { FFMA2(acc_if[k - 2], pix, wif2); FFMA2(acc_og[k - 2], pix, wog2); }
            }
        }
    }

    // Epilogue: gates + state update for 8 pixels.
    const float bi  = bc[hid];
    const float bfv = bc[hid + 16];
    const float bo  = bc[hid + 32];
    const float bg  = bc[hid + 48];
    const int base = ((b * HID + hid) << 16) + ((y0 + row) << 8) + x0 + xg * 8;

    float cold[8];
    if (!first) {
        float4 ca = *(const float4*)(g_c + base);
        float4 cb = *(const float4*)(g_c + base + 4);
        cold[0] = ca.x; cold[1] = ca.y; cold[2] = ca.z; cold[3] = ca.w;
        cold[4] = cb.x; cold[5] = cb.y; cold[6] = cb.z; cold[7] = cb.w;
    } else {
        #pragma unroll
        for (int p = 0; p < 8; ++p) cold[p] = 0.0f;
    }

    float cn[8], hn[8];
    #pragma unroll
    for (int p = 0; p < 8; ++p) {
        float iv, fv, ov, gv;
        upk2(acc_if[p], iv, fv);
        upk2(acc_og[p], ov, gv);
        float i = sig_(iv + bi),  f = sig_(fv + bfv);
        float o = sig_(ov + bo),  g = tanh_(gv + bg);
        float c = f * cold[p] + i * g;
        cn[p] = c; hn[p] = o * tanh_(c);
    }
    *(float4*)(g_c + base)        = make_float4(cn[0], cn[1], cn[2], cn[3]);
    *(float4*)(g_c + base + 4)    = make_float4(cn[4], cn[5], cn[6], cn[7]);
    *(float4*)(h_next + base)     = make_float4(hn[0], hn[1], hn[2], hn[3]);
    *(float4*)(h_next + base + 4) = make_float4(hn[4], hn[5], hn[6], hn[7]);
}

// Final 1x1 conv over h_last (g_h[0] after 12 steps).
__global__ void final_conv_kernel(const float* __restrict__ Wf,
                                  const float* __restrict__ bfin,
                                  float* __restrict__ out)
{
    const int total4 = BATCH * IMG * IMG / 4;
    int idx4 = blockIdx.x * blockDim.x + threadIdx.x;
    if (idx4 >= total4) return;
    const float* h = g_h[TSTEPS & 1];
    int b    = idx4 >> 14;
    int pix4 = idx4 & 16383;
    float w[HID];
    #pragma unroll
    for (int j = 0; j < HID; ++j) w[j] = Wf[j];
    float bv = bfin[0];
    float4 a; a.x = bv; a.y = bv; a.z = bv; a.w = bv;
    #pragma unroll
    for (int j = 0; j < HID; ++j) {
        float4 v = *(const float4*)(h + ((b * HID + j) << 16) + pix4 * 4);
        a.x += w[j] * v.x; a.y += w[j] * v.y;
        a.z += w[j] * v.z; a.w += w[j] * v.w;
    }
    ((float4*)out)[idx4] = a;
}

extern "C" void kernel_launch(void* const* d_in, const int* in_sizes, int n_in,
                              void* d_out, int out_size)
{
    const float* x  = (const float*)d_in[0];
    const float* Wc = (const float*)d_in[1];
    const float* bc = (const float*)d_in[2];
    const float* Wf = (const float*)d_in[3];
    const float* bf = (const float*)d_in[4];
    float* out = (float*)d_out;

    cudaFuncSetAttribute(lstm_step_kernel,
                         cudaFuncAttributeMaxDynamicSharedMemorySize, SMEM_BYTES);

    dim3 grid(IMG / TILE, IMG / TILE, BATCH);
    for (int t = 0; t < TSTEPS; ++t)
        lstm_step_kernel<<<grid, NTHREADS, SMEM_BYTES>>>(x, Wc, bc, t);

    const int total4 = BATCH * IMG * IMG / 4;
    final_conv_kernel<<<(total4 + 255) / 256, 256>>>(Wf, bf, out);
}

// round 4
// speedup vs baseline: 1.3639x; 1.0100x over previous
#include <cuda_runtime.h>

#define BATCH   8
#define TSTEPS  12
#define CIN_X   5
#define HID     16
#define CIN_ALL (CIN_X + HID)      /* 21 */
#define IMG     256
#define WPERC   (CIN_ALL * 9)      /* 189 taps per hid per gate */
#define TILE    16
#define NTHREADS 512

/* smem layout:
   floats [0, 12096):  weights reordered [hid16][ci21][tap9][gate4] (48384 B)
   u64    after:       pixel tile dup (v,v): [21 ci][18 r][18 u64]  (54432 B)
   row stride 18 u64 = 36 floats -> 36 mod 32 = 4 -> conflict-free LDS.128
*/
#define W_FLOATS  (64 * WPERC)               /* 12096 */
#define TSTRIDE   18                         /* u64 per row */
#define T_PER_CI  (18 * TSTRIDE)             /* 324 u64 */
#define TILE_U64  (CIN_ALL * T_PER_CI)       /* 6804 u64 */
#define SMEM_BYTES (W_FLOATS * 4 + TILE_U64 * 8)   /* 48384 + 54432 = 102816 */

__device__ float g_h[2][BATCH * HID * IMG * IMG];
__device__ float g_c[BATCH * HID * IMG * IMG];

typedef unsigned long long u64;

__device__ __forceinline__ u64 pk2(float lo, float hi) {
    u64 r; asm("mov.b64 %0, {%1, %2};" : "=l"(r) : "f"(lo), "f"(hi)); return r;
}
__device__ __forceinline__ void upk2(u64 v, float &lo, float &hi) {
    asm("mov.b64 {%0, %1}, %2;" : "=f"(lo), "=f"(hi) : "l"(v));
}
#define FFMA2(acc, a, b) asm("fma.rn.f32x2 %0, %1, %2, %0;" : "+l"(acc) : "l"(a), "l"(b))

__device__ __forceinline__ float sig_(float x)  { return 1.0f / (1.0f + __expf(-x)); }
__device__ __forceinline__ float tanh_(float x) { return 2.0f / (1.0f + __expf(-2.0f * x)) - 1.0f; }

// Fused ConvLSTM step. Block = 16x16 tile x 16 hid (warp==hid), 2 CTAs/SM.
// FFMA2 pairs gates: acc_if[p]=(i,f), acc_og[p]=(o,g), 8 pixels/thread.
// Weight fetch: 1 broadcast LDS.128 = both gate pairs, zero movs.
// Pixel fetch: 5 aligned conflict-free LDS.128 per (ci,ky) = 10 dup pixels.
__global__ void __launch_bounds__(NTHREADS, 2)
lstm_step_kernel(const float* __restrict__ xall, const float* __restrict__ Wc,
                 const float* __restrict__ bc, int t)
{
    extern __shared__ float smem[];
    float* s_w = smem;                       // [64][189] -> [hid][tap][gate4]
    u64*   s_t = (u64*)(smem + W_FLOATS);    // [21][18][18] dup pixels

    const int tid = threadIdx.x;
    const int b  = blockIdx.z;
    const int y0 = blockIdx.y * TILE;
    const int x0 = blockIdx.x * TILE;
    const int first = (t == 0);
    const int ncin  = first ? CIN_X : CIN_ALL;

    const float* h_prev = g_h[t & 1];
    float*       h_next = g_h[(t + 1) & 1];

    // Weights -> smem reordered: dst[hid][tap][gate4]; src Wc[(g*16+hid)*189+tap]
    #pragma unroll 1
    for (int i = tid; i < 64 * WPERC / 4; i += NTHREADS) {   // (hid, tap) items
        int hid = i / WPERC;
        int tap = i - hid * WPERC;
        float4 v;
        v.x = Wc[(hid     ) * WPERC + tap];
        v.y = Wc[(hid + 16) * WPERC + tap];
        v.z = Wc[(hid + 32) * WPERC + tap];
        v.w = Wc[(hid + 48) * WPERC + tap];
        ((float4*)s_w)[hid * WPERC + tap] = v;
    }
    // Input tile (+halo) duplicated (v,v) -> smem.
    {
        const int ntile = ncin * 18 * 18;
        #pragma unroll 1
        for (int i = tid; i < ntile; i += NTHREADS) {
            int ci  = i / (18 * 18);
            int rem = i - ci * (18 * 18);
            int r   = rem / 18;
            int mi  = rem - r * 18;                 // 0..17 == col -1..16
            int gy = y0 + r - 1, gx = x0 + mi - 1;
            float v = 0.0f;
            if ((unsigned)gy < IMG && (unsigned)gx < IMG) {
                if (ci < CIN_X)
                    v = xall[(((b * TSTEPS + t) * CIN_X + ci) << 16) + (gy << 8) + gx];
                else
                    v = h_prev[((b * HID + (ci - CIN_X)) << 16) + (gy << 8) + gx];
            }
            s_t[ci * T_PER_CI + r * TSTRIDE + mi] = pk2(v, v);
        }
    }
    __syncthreads();

    const int hid  = tid >> 5;       // warp-uniform
    const int lane = tid & 31;
    const int row  = lane & 15;
    const int xg   = lane >> 4;      // pixels xg*8 .. xg*8+7

    u64 acc_if[8], acc_og[8];
    #pragma unroll
    for (int p = 0; p < 8; ++p) { acc_if[p] = 0ULL; acc_og[p] = 0ULL; }

    #pragma unroll 1
    for (int ci = 0; ci < ncin; ++ci) {
        const u64* tbase = s_t + ci * T_PER_CI + row * TSTRIDE + xg * 8;
        const ulonglong2* wci = (const ulonglong2*)s_w + hid * WPERC + ci * 9;
        #pragma unroll
        for (int ky = 0; ky < 3; ++ky) {
            const u64* tr = tbase + ky * TSTRIDE;   // even u64 offset -> 16B aligned
            ulonglong2 q0 = *(const ulonglong2*)(tr + 0);
            ulonglong2 q1 = *(const ulonglong2*)(tr + 2);
            ulonglong2 q2 = *(const ulonglong2*)(tr + 4);
            ulonglong2 q3 = *(const ulonglong2*)(tr + 6);
            ulonglong2 q4 = *(const ulonglong2*)(tr + 8);
            // weight packs: .x = (wi,wf), .y = (wo,wg) — no movs
            ulonglong2 w0 = wci[ky * 3 + 0];
            ulonglong2 w1 = wci[ky * 3 + 1];
            ulonglong2 w2 = wci[ky * 3 + 2];
            u64 pix[10] = { q0.x, q0.y, q1.x, q1.y, q2.x,
                            q2.y, q3.x, q3.y, q4.x, q4.y };
            #pragma unroll
            for (int k = 0; k < 10; ++k) {
                if (k <= 7)           { FFMA2(acc_if[k],     pix[k], w0.x); FFMA2(acc_og[k],     pix[k], w0.y); }
                if (k >= 1 && k <= 8) { FFMA2(acc_if[k - 1], pix[k], w1.x); FFMA2(acc_og[k - 1], pix[k], w1.y); }
                if (k >= 2)           { FFMA2(acc_if[k - 2], pix[k], w2.x); FFMA2(acc_og[k - 2], pix[k], w2.y); }
            }
        }
    }

    // Epilogue: gates + state update for 8 pixels.
    const float bi  = bc[hid];
    const float bfv = bc[hid + 16];
    const float bo  = bc[hid + 32];
    const float bg  = bc[hid + 48];
    const int base = ((b * HID + hid) << 16) + ((y0 + row) << 8) + x0 + xg * 8;

    float cold[8];
    if (!first) {
        float4 ca = *(const float4*)(g_c + base);
        float4 cb = *(const float4*)(g_c + base + 4);
        cold[0] = ca.x; cold[1] = ca.y; cold[2] = ca.z; cold[3] = ca.w;
        cold[4] = cb.x; cold[5] = cb.y; cold[6] = cb.z; cold[7] = cb.w;
    } else {
        #pragma unroll
        for (int p = 0; p < 8; ++p) cold[p] = 0.0f;
    }

    float cn[8], hn[8];
    #pragma unroll
    for (int p = 0; p < 8; ++p) {
        float iv, fv, ov, gv;
        upk2(acc_if[p], iv, fv);
        upk2(acc_og[p], ov, gv);
        float i = sig_(iv + bi),  f = sig_(fv + bfv);
        float o = sig_(ov + bo),  g = tanh_(gv + bg);
        float c = f * cold[p] + i * g;
        cn[p] = c; hn[p] = o * tanh_(c);
    }
    *(float4*)(g_c + base)        = make_float4(cn[0], cn[1], cn[2], cn[3]);
    *(float4*)(g_c + base + 4)    = make_float4(cn[4], cn[5], cn[6], cn[7]);
    *(float4*)(h_next + base)     = make_float4(hn[0], hn[1], hn[2], hn[3]);
    *(float4*)(h_next + base + 4) = make_float4(hn[4], hn[5], hn[6], hn[7]);
}

// Final 1x1 conv over h_last (g_h[0] after 12 steps).
__global__ void final_conv_kernel(const float* __restrict__ Wf,
                                  const float* __restrict__ bfin,
                                  float* __restrict__ out)
{
    const int total4 = BATCH * IMG * IMG / 4;
    int idx4 = blockIdx.x * blockDim.x + threadIdx.x;
    if (idx4 >= total4) return;
    const float* h = g_h[TSTEPS & 1];
    int b    = idx4 >> 14;
    int pix4 = idx4 & 16383;
    float w[HID];
    #pragma unroll
    for (int j = 0; j < HID; ++j) w[j] = Wf[j];
    float bv = bfin[0];
    float4 a; a.x = bv; a.y = bv; a.z = bv; a.w = bv;
    #pragma unroll
    for (int j = 0; j < HID; ++j) {
        float4 v = *(const float4*)(h + ((b * HID + j) << 16) + pix4 * 4);
        a.x += w[j] * v.x; a.y += w[j] * v.y;
        a.z += w[j] * v.z; a.w += w[j] * v.w;
    }
    ((float4*)out)[idx4] = a;
}

extern "C" void kernel_launch(void* const* d_in, const int* in_sizes, int n_in,
                              void* d_out, int out_size)
{
    const float* x  = (const float*)d_in[0];
    const float* Wc = (const float*)d_in[1];
    const float* bc = (const float*)d_in[2];
    const float* Wf = (const float*)d_in[3];
    const float* bf = (const float*)d_in[4];
    float* out = (float*)d_out;

    cudaFuncSetAttribute(lstm_step_kernel,
                         cudaFuncAttributeMaxDynamicSharedMemorySize, SMEM_BYTES);

    dim3 grid(IMG / TILE, IMG / TILE, BATCH);
    for (int t = 0; t < TSTEPS; ++t)
        lstm_step_kernel<<<grid, NTHREADS, SMEM_BYTES>>>(x, Wc, bc, t);

    const int total4 = BATCH * IMG * IMG / 4;
    final_conv_kernel<<<(total4 + 255) / 256, 256>>>(Wf, bf, out);
}